// round 13
// baseline (speedup 1.0000x reference)
#include <cuda_runtime.h>
#include <cuda_fp16.h>
#include <cuda_bf16.h>
#include <cstdint>

#define NVOX 32768
#define SCALE 0.17677669529663689f   // 1/sqrt(32)

// Scratch (allocation-free: device globals)
__device__ __align__(16) __half   g_qh[NVOX * 128];   // [v][128] q, fp16
__device__ __align__(16) __half   g_kv[NVOX * 256];   // [v][ k:128 | v:128 ] fp16
__device__ __align__(16) uint32_t g_ah[64 * NVOX];    // [c2][v] attn out, half2 ch-pairs
__device__ __align__(16) uint2    g_wfrag[3 * 8 * 16 * 32];  // qkv_w frags (bf16 hi)
__device__ __align__(16) uint2    g_pfrag[8 * 16 * 32];      // proj_w frags (bf16 hi)

// ---------------------------------------------------------------------------
// PTX helpers
// ---------------------------------------------------------------------------
__device__ __forceinline__ uint32_t smem_u32(const void* p) {
    uint32_t a;
    asm("{ .reg .u64 t; cvta.to.shared.u64 t, %1; cvt.u32.u64 %0, t; }" : "=r"(a) : "l"(p));
    return a;
}
__device__ __forceinline__ void ldsm4(uint32_t* f, uint32_t addr) {
    asm volatile("ldmatrix.sync.aligned.m8n8.x4.shared.b16 {%0,%1,%2,%3}, [%4];"
        : "=r"(f[0]), "=r"(f[1]), "=r"(f[2]), "=r"(f[3]) : "r"(addr));
}
__device__ __forceinline__ void cpasync16(uint32_t dst, const void* src) {
    asm volatile("cp.async.cg.shared.global [%0], [%1], 16;" :: "r"(dst), "l"(src));
}
#define CP_COMMIT() asm volatile("cp.async.commit_group;" ::: "memory")
#define CP_WAIT(n)  asm volatile("cp.async.wait_group %0;" :: "n"(n) : "memory")

// warp mma: D(16x8,f32) += A(16x16 bf16,row) * B(16x8 bf16,col)
__device__ __forceinline__ void mma16816(float* d, const uint32_t* a, const uint32_t* b) {
    asm volatile(
        "mma.sync.aligned.m16n8k16.row.col.f32.bf16.bf16.f32 "
        "{%0,%1,%2,%3}, {%4,%5,%6,%7}, {%8,%9}, {%0,%1,%2,%3};"
        : "+f"(d[0]), "+f"(d[1]), "+f"(d[2]), "+f"(d[3])
        : "r"(a[0]), "r"(a[1]), "r"(a[2]), "r"(a[3]), "r"(b[0]), "r"(b[1]));
}

// convert 8 fp32 -> 8 bf16, packed as uint4
__device__ __forceinline__ uint4 pack8(const float* v) {
    uint32_t h[4];
    #pragma unroll
    for (int i = 0; i < 4; i++) {
        __nv_bfloat16 h0 = __float2bfloat16_rn(v[2 * i]);
        __nv_bfloat16 h1 = __float2bfloat16_rn(v[2 * i + 1]);
        h[i] = (uint32_t)__bfloat16_as_ushort(h0) | ((uint32_t)__bfloat16_as_ushort(h1) << 16);
    }
    return make_uint4(h[0], h[1], h[2], h[3]);
}

// pack float2 -> bf16x2
__device__ __forceinline__ uint32_t packbf2(float a, float b) {
    __nv_bfloat16 h0 = __float2bfloat16_rn(a);
    __nv_bfloat16 h1 = __float2bfloat16_rn(b);
    return (uint32_t)__bfloat16_as_ushort(h0) | ((uint32_t)__bfloat16_as_ushort(h1) << 16);
}

// A tile geometry: bf16 [row][k], row stride 136 elems (272 B)
#define RSTRIDE 272
#define B_CHUNK 32768              // one N-chunk of fragments (4096 uint2)
#define SM_LNQKV (34816 + 2 * B_CHUNK)   // A + double-buffered B = 100352
#define SM_PROJ  67584             // max(A 34816 + B 32768, ts 128*132*4)

// ---------------------------------------------------------------------------
// Kernel 0: pre-fragment weights (bf16 hi) into per-lane LDG layout.
// lane holds n = nt*8 + (lane>>2), k = ks*16 + (lane&3)*2 (+1, +8, +9).
// ---------------------------------------------------------------------------
__global__ void prep_kernel(const float* __restrict__ qw, const float* __restrict__ pw) {
    int t = blockIdx.x * 256 + threadIdx.x;
    int lane = t & 31, nt = (t >> 5) & 15, ks = (t >> 9) & 7, chunk = t >> 12;
    int n = nt * 8 + (lane >> 2);
    int kb = ks * 16 + (lane & 3) * 2;
    if (t < 3 * 8 * 16 * 32) {
        const float* wr = qw + (chunk * 128 + n) * 128;
        float2 a = __ldg((const float2*)(wr + kb));
        float2 b = __ldg((const float2*)(wr + kb + 8));
        g_wfrag[t] = make_uint2(packbf2(a.x, a.y), packbf2(b.x, b.y));
    }
    if (t < 8 * 16 * 32) {
        const float* wr = pw + n * 128;
        float2 a = __ldg((const float2*)(wr + kb));
        float2 b = __ldg((const float2*)(wr + kb + 8));
        g_pfrag[t] = make_uint2(packbf2(a.x, a.y), packbf2(b.x, b.y));
    }
}

// ---------------------------------------------------------------------------
// Kernel 1: LN + QKV GEMM (single bf16), B staged in smem via cp.async.
// CTA = 128 voxels, 256 thr, 2 CTA/SM.
// smem: A [0,34816) | B0 [34816,67584) | B1 [67584,100352)
// ---------------------------------------------------------------------------
__global__ void __launch_bounds__(256, 2) lnqkv_mma(
    const float* __restrict__ x, const float* __restrict__ gam,
    const float* __restrict__ bet, const float* __restrict__ qb)
{
    extern __shared__ char smem[];
    const int tid = threadIdx.x, lane = tid & 31, wid = tid >> 5;
    const int vb = blockIdx.x * 128;
    const uint32_t sb = smem_u32(smem);

    // prefetch B chunk 0 into buffer 0
    #pragma unroll
    for (int t = 0; t < 8; t++) {
        int idx = tid + t * 256;               // 2048 x 16B = 32KB
        cpasync16(sb + 34816 + idx * 16, (const char*)g_wfrag + idx * 16);
    }
    CP_COMMIT();

    // ---- LayerNorm: 4 threads/voxel, 2 passes of 64 voxels ----
    #pragma unroll
    for (int vp = 0; vp < 2; vp++) {
        const int v = vp * 64 + (tid >> 2), q = tid & 3;
        float r[32];
        const float* xp = x + (q * 32) * NVOX + vb + v;
        #pragma unroll 8
        for (int i = 0; i < 32; i++) r[i] = xp[i * NVOX];
        float s = 0.f, s2 = 0.f;
        #pragma unroll
        for (int i = 0; i < 32; i++) { s += r[i]; s2 += r[i] * r[i]; }
        s  += __shfl_xor_sync(0xffffffffu, s, 1);  s  += __shfl_xor_sync(0xffffffffu, s, 2);
        s2 += __shfl_xor_sync(0xffffffffu, s2, 1); s2 += __shfl_xor_sync(0xffffffffu, s2, 2);
        float mu = s * (1.f / 128.f);
        float var = s2 * (1.f / 128.f) - mu * mu;
        float rs = rsqrtf(var + 1e-5f);
        #pragma unroll 8
        for (int i = 0; i < 32; i++) {
            int c = q * 32 + i;
            r[i] = (r[i] - mu) * rs * __ldg(&gam[c]) + __ldg(&bet[c]);
        }
        #pragma unroll
        for (int jj = 0; jj < 4; jj++) {
            int chunk = q * 4 + jj;
            *(uint4*)(smem + v * RSTRIDE + chunk * 16) = pack8(&r[8 * jj]);
        }
    }

    const int g = lane >> 2, t2 = lane & 3;
    const int m0 = (wid & 3) * 32, nhalf = wid >> 2, n0 = nhalf * 64;
    const uint32_t aA = sb + (m0 + (lane & 15)) * RSTRIDE + (lane >> 4) * 16;
    const int bidx = (nhalf * 256 + lane) * 8;   // byte offset of this lane's frag base

    #pragma unroll
    for (int nc = 0; nc < 3; nc++) {
        if (nc < 2) {                            // prefetch next chunk into other buffer
            uint32_t boff = 34816 + ((nc + 1) & 1) * B_CHUNK;
            #pragma unroll
            for (int t = 0; t < 8; t++) {
                int idx = tid + t * 256;
                cpasync16(sb + boff + idx * 16,
                          (const char*)g_wfrag + (nc + 1) * B_CHUNK + idx * 16);
            }
            CP_COMMIT();
            CP_WAIT(1);
        } else {
            CP_WAIT(0);
        }
        __syncthreads();                         // current buffer + A visible

        const char* bbase = smem + 34816 + (nc & 1) * B_CHUNK + bidx;

        float acc[2][8][4];
        #pragma unroll
        for (int nt = 0; nt < 8; nt++) {
            float b0 = __ldg(&qb[nc * 128 + n0 + nt * 8 + t2 * 2]);
            float b1 = __ldg(&qb[nc * 128 + n0 + nt * 8 + t2 * 2 + 1]);
            acc[0][nt][0] = b0; acc[0][nt][1] = b1; acc[0][nt][2] = b0; acc[0][nt][3] = b1;
            acc[1][nt][0] = b0; acc[1][nt][1] = b1; acc[1][nt][2] = b0; acc[1][nt][3] = b1;
        }

        #pragma unroll
        for (int ks = 0; ks < 8; ks++) {
            uint2 B[8];
            #pragma unroll
            for (int nt = 0; nt < 8; nt++)
                B[nt] = *(const uint2*)(bbase + (ks * 512 + nt * 32) * 8);
            uint32_t Ah[2][4];
            ldsm4(Ah[0], aA + ks * 32);
            ldsm4(Ah[1], aA + 16 * RSTRIDE + ks * 32);
            #pragma unroll
            for (int nt = 0; nt < 8; nt++) {
                uint32_t bh[2] = { B[nt].x, B[nt].y };
                mma16816(acc[0][nt], Ah[0], bh);
                mma16816(acc[1][nt], Ah[1], bh);
            }
        }

        // epilogue: fp16 outputs
        #pragma unroll
        for (int mt = 0; mt < 2; mt++) {
            int row = vb + m0 + mt * 16 + g;
            #pragma unroll
            for (int nt = 0; nt < 8; nt++) {
                int col = n0 + nt * 8 + t2 * 2;
                __half2 h0 = __floats2half2_rn(acc[mt][nt][0], acc[mt][nt][1]);
                __half2 h1 = __floats2half2_rn(acc[mt][nt][2], acc[mt][nt][3]);
                if (nc == 0) {
                    ((uint32_t*)g_qh)[row * 64 + (col >> 1)]       = *(uint32_t*)&h0;
                    ((uint32_t*)g_qh)[(row + 8) * 64 + (col >> 1)] = *(uint32_t*)&h1;
                } else {
                    int base = (nc == 1) ? 0 : 64;
                    ((uint32_t*)g_kv)[row * 128 + base + (col >> 1)]       = *(uint32_t*)&h0;
                    ((uint32_t*)g_kv)[(row + 8) * 128 + base + (col >> 1)] = *(uint32_t*)&h1;
                }
            }
        }
        if (nc < 2) __syncthreads();     // done reading buf[nc&1] before it's overwritten
    }
}

// ---------------------------------------------------------------------------
// Kernel 2: 27-neighbor attention, fp16 K/V/Q, single-phase halo, HFMA2.
// Block = 4x4x4 spatial tile x 4 heads, 256 threads, 2 blocks/SM.
// ---------------------------------------------------------------------------
__global__ void __launch_bounds__(256, 2) attn_kernel() {
    extern __shared__ char smem[];
    char* ksm = smem;
    char* vsm = smem + 55296;
    const int tid = threadIdx.x;
    const int b = blockIdx.x;
    const int tx = b >> 6, ty = (b >> 3) & 7, tz = b & 7;
    const int hx0 = tx * 4 - 1, hy0 = ty * 4 - 1, hz0 = tz * 4 - 1;

    const int j = tid & 63, h = tid >> 6;
    const int lx = j >> 4, ly = (j >> 2) & 3, lz = j & 3;
    const int gx = tx * 4 + lx, gy = ty * 4 + ly, gz = tz * 4 + lz;
    const int gv0 = (gx << 10) + (gy << 5) + gz;

    // halo load: 216 positions x 512B (K 256 + V 256), 16B chunks, swizzled
    for (int i = tid; i < 216 * 32; i += 256) {
        int p = i >> 5, c = i & 31;
        int hx = p / 36, r = p - hx * 36, hy = r / 6, hz = r - hy * 6;
        int ggx = min(max(hx0 + hx, 0), 31);
        int ggy = min(max(hy0 + hy, 0), 31);
        int ggz = min(max(hz0 + hz, 0), 31);
        int gv = (ggx << 10) + (ggy << 5) + ggz;
        uint4 t = __ldg((const uint4*)((const char*)g_kv + gv * 512 + c * 16));
        char* base = (c < 16) ? ksm : vsm;
        int cc = c & 15;
        *(uint4*)(base + p * 256 + ((cc ^ (p & 15)) << 4)) = t;
    }

    // q -> half2, pre-scaled
    __half2 qh[16];
    {
        const __half2 s2 = __float2half2_rn(SCALE);
        const uint4* qp = (const uint4*)&g_qh[gv0 * 128 + h * 32];
        #pragma unroll
        for (int c = 0; c < 4; c++) {
            uint4 t = __ldg(qp + c);
            const __half2* q2 = (const __half2*)&t;
            qh[c * 4 + 0] = __hmul2(q2[0], s2);
            qh[c * 4 + 1] = __hmul2(q2[1], s2);
            qh[c * 4 + 2] = __hmul2(q2[2], s2);
            qh[c * 4 + 3] = __hmul2(q2[3], s2);
        }
    }
    __syncthreads();

    const int sx = min(max(gx - 1, 0), 29) - hx0;
    const int sy = min(max(gy - 1, 0), 29) - hy0;
    const int sz = min(max(gz - 1, 0), 29) - hz0;

    const __half2 z2 = __float2half2_rn(0.f);
    float sc[27];
    #pragma unroll
    for (int dx = 0; dx < 3; dx++)
    #pragma unroll
    for (int dy = 0; dy < 3; dy++)
    #pragma unroll
    for (int dz = 0; dz < 3; dz++) {
        int p = (sx + dx) * 36 + (sy + dy) * 6 + (sz + dz);
        const char* kb = ksm + p * 256;
        int psw = p & 15;
        __half2 a0 = z2, a1 = z2, a2 = z2, a3 = z2;
        #pragma unroll
        for (int cc = 0; cc < 4; cc++) {
            uint4 t = *(const uint4*)(kb + (((h * 4 + cc) ^ psw) << 4));
            const __half2* kk = (const __half2*)&t;
            a0 = __hfma2(qh[cc * 4 + 0], kk[0], a0);
            a1 = __hfma2(qh[cc * 4 + 1], kk[1], a1);
            a2 = __hfma2(qh[cc * 4 + 2], kk[2], a2);
            a3 = __hfma2(qh[cc * 4 + 3], kk[3], a3);
        }
        __half2 as = __hadd2(__hadd2(a0, a1), __hadd2(a2, a3));
        float2 f = __half22float2(as);
        sc[dx * 9 + dy * 3 + dz] = f.x + f.y;
    }

    // softmax (fp32)
    float mx = sc[0];
    #pragma unroll
    for (int n = 1; n < 27; n++) mx = fmaxf(mx, sc[n]);
    float sum = 0.f;
    #pragma unroll
    for (int n = 0; n < 27; n++) { float e = __expf(sc[n] - mx); sc[n] = e; sum += e; }
    float inv = __fdividef(1.f, sum);

    // weighted V sum (HFMA2)
    __half2 out[16];
    #pragma unroll
    for (int i = 0; i < 16; i++) out[i] = z2;

    #pragma unroll
    for (int dx = 0; dx < 3; dx++)
    #pragma unroll
    for (int dy = 0; dy < 3; dy++)
    #pragma unroll
    for (int dz = 0; dz < 3; dz++) {
        int p = (sx + dx) * 36 + (sy + dy) * 6 + (sz + dz);
        const char* vbp = vsm + p * 256;
        int psw = p & 15;
        __half2 wh = __float2half2_rn(sc[dx * 9 + dy * 3 + dz]);
        #pragma unroll
        for (int cc = 0; cc < 4; cc++) {
            uint4 t = *(const uint4*)(vbp + (((h * 4 + cc) ^ psw) << 4));
            const __half2* vv = (const __half2*)&t;
            out[cc * 4 + 0] = __hfma2(wh, vv[0], out[cc * 4 + 0]);
            out[cc * 4 + 1] = __hfma2(wh, vv[1], out[cc * 4 + 1]);
            out[cc * 4 + 2] = __hfma2(wh, vv[2], out[cc * 4 + 2]);
            out[cc * 4 + 3] = __hfma2(wh, vv[3], out[cc * 4 + 3]);
        }
    }

    // transpose through smem -> uint4 stores to g_ah[c2][v]
    __syncthreads();
    uint32_t* buf = (uint32_t*)ksm;          // [64 c2][64 j]
    #pragma unroll
    for (int c = 0; c < 16; c++) {
        float2 f = __half22float2(out[c]);
        __half2 o = __floats2half2_rn(f.x * inv, f.y * inv);
        buf[(h * 16 + c) * 64 + j] = *(uint32_t*)&o;
    }
    __syncthreads();
    for (int i = tid; i < 64 * 16; i += 256) {
        int c2 = i >> 4, r = i & 15;
        int vlx = r >> 2, vly = r & 3;
        uint4 t = *(const uint4*)&buf[c2 * 64 + vlx * 16 + vly * 4];
        *(uint4*)&g_ah[c2 * NVOX + (((tx * 4 + vlx) << 10) + ((ty * 4 + vly) << 5) + tz * 4)] = t;
    }
}

// ---------------------------------------------------------------------------
// Kernel 3: proj GEMM (single bf16), B staged in smem.  2 CTA/SM.
// smem: A [0,34816) | B [34816,67584); ts overlays [0,67584)
// ---------------------------------------------------------------------------
__global__ void __launch_bounds__(256, 2) proj_mma(
    const float* __restrict__ x, const float* __restrict__ pb, float* __restrict__ out)
{
    extern __shared__ char smem[];
    const int tid = threadIdx.x, lane = tid & 31, wid = tid >> 5;
    const int vb = blockIdx.x * 128;
    const uint32_t sb = smem_u32(smem);

    // stage B fragments via cp.async (overlaps A conversion's global reads)
    #pragma unroll
    for (int t = 0; t < 8; t++) {
        int idx = tid + t * 256;
        cpasync16(sb + 34816 + idx * 16, (const char*)g_pfrag + idx * 16);
    }
    CP_COMMIT();

    // A conversion: g_ah[c2][v] -> A hi tile, 4 thr/voxel, 2 passes
    #pragma unroll
    for (int vp = 0; vp < 2; vp++) {
        const int v = vp * 64 + (tid >> 2), q = tid & 3;
        float r[32];
        const uint32_t* ap = g_ah + (q * 16) * NVOX + vb + v;
        #pragma unroll 8
        for (int c2 = 0; c2 < 16; c2++) {
            uint32_t u = ap[c2 * NVOX];
            float2 f = __half22float2(*(const __half2*)&u);
            r[2 * c2] = f.x; r[2 * c2 + 1] = f.y;
        }
        #pragma unroll
        for (int jj = 0; jj < 4; jj++) {
            int chunk = q * 4 + jj;
            *(uint4*)(smem + v * RSTRIDE + chunk * 16) = pack8(&r[8 * jj]);
        }
    }
    CP_WAIT(0);
    __syncthreads();

    const int g = lane >> 2, t2 = lane & 3;
    const int m0 = (wid & 3) * 32, nhalf = wid >> 2, n0 = nhalf * 64;
    const uint32_t aA = sb + (m0 + (lane & 15)) * RSTRIDE + (lane >> 4) * 16;
    const char* bbase = smem + 34816 + (nhalf * 256 + lane) * 8;

    float acc[2][8][4];
    #pragma unroll
    for (int nt = 0; nt < 8; nt++) {
        float b0 = __ldg(&pb[n0 + nt * 8 + t2 * 2]);
        float b1 = __ldg(&pb[n0 + nt * 8 + t2 * 2 + 1]);
        acc[0][nt][0] = b0; acc[0][nt][1] = b1; acc[0][nt][2] = b0; acc[0][nt][3] = b1;
        acc[1][nt][0] = b0; acc[1][nt][1] = b1; acc[1][nt][2] = b0; acc[1][nt][3] = b1;
    }

    #pragma unroll
    for (int ks = 0; ks < 8; ks++) {
        uint2 B[8];
        #pragma unroll
        for (int nt = 0; nt < 8; nt++)
            B[nt] = *(const uint2*)(bbase + (ks * 512 + nt * 32) * 8);
        uint32_t Ah[2][4];
        ldsm4(Ah[0], aA + ks * 32);
        ldsm4(Ah[1], aA + 16 * RSTRIDE + ks * 32);
        #pragma unroll
        for (int nt = 0; nt < 8; nt++) {
            uint32_t bh[2] = { B[nt].x, B[nt].y };
            mma16816(acc[0][nt], Ah[0], bh);
            mma16816(acc[1][nt], Ah[1], bh);
        }
    }

    // transpose D through smem: ts[c][v], stride 132
    __syncthreads();
    float* ts = (float*)smem;
    #pragma unroll
    for (int mt = 0; mt < 2; mt++) {
        int row = m0 + mt * 16 + g;
        #pragma unroll
        for (int nt = 0; nt < 8; nt++) {
            int col = n0 + nt * 8 + t2 * 2;
            ts[col * 132 + row]           = acc[mt][nt][0];
            ts[(col + 1) * 132 + row]     = acc[mt][nt][1];
            ts[col * 132 + row + 8]       = acc[mt][nt][2];
            ts[(col + 1) * 132 + row + 8] = acc[mt][nt][3];
        }
    }
    __syncthreads();

    // residual + coalesced channel-major stores
    for (int i = tid; i < 128 * 32; i += 256) {
        int c = i >> 5, vq = i & 31;
        int off = c * NVOX + vb + vq * 4;
        float4 t = *(const float4*)&ts[c * 132 + vq * 4];
        float4 xr = *(const float4*)&x[off];
        *(float4*)&out[off] = make_float4(t.x + xr.x, t.y + xr.y, t.z + xr.z, t.w + xr.w);
    }
}

// ---------------------------------------------------------------------------
extern "C" void kernel_launch(void* const* d_in, const int* in_sizes, int n_in,
                              void* d_out, int out_size)
{
    const float* x   = (const float*)d_in[0];
    const float* gam = (const float*)d_in[1];
    const float* bet = (const float*)d_in[2];
    const float* qw  = (const float*)d_in[3];
    const float* qb  = (const float*)d_in[4];
    const float* pw  = (const float*)d_in[5];
    const float* pb  = (const float*)d_in[6];
    float* out = (float*)d_out;

    const int SMEM_ATTN = 110592;

    cudaFuncSetAttribute(lnqkv_mma,   cudaFuncAttributeMaxDynamicSharedMemorySize, SM_LNQKV);
    cudaFuncSetAttribute(attn_kernel, cudaFuncAttributeMaxDynamicSharedMemorySize, SMEM_ATTN);
    cudaFuncSetAttribute(proj_mma,    cudaFuncAttributeMaxDynamicSharedMemorySize, SM_PROJ);

    prep_kernel<<<48, 256>>>(qw, pw);
    lnqkv_mma<<<256, 256, SM_LNQKV>>>(x, gam, bet, qb);
    attn_kernel<<<512, 256, SMEM_ATTN>>>();
    proj_mma<<<256, 256, SM_PROJ>>>(x, pb, out);
}

// round 14
// speedup vs baseline: 1.0187x; 1.0187x over previous
#include <cuda_runtime.h>
#include <cuda_fp16.h>
#include <cuda_bf16.h>
#include <cstdint>

#define NVOX 32768
#define SCALE 0.17677669529663689f   // 1/sqrt(32)

// Scratch (allocation-free: device globals)
__device__ __align__(16) __half   g_qh[NVOX * 128];   // [v][128] q, fp16
__device__ __align__(16) __half   g_kv[NVOX * 256];   // [v][ k:128 | v:128 ] fp16
__device__ __align__(16) uint32_t g_ah[64 * NVOX];    // [c2][v] attn out, half2 ch-pairs
__device__ __align__(16) uint2    g_wfrag[3 * 8 * 16 * 32];  // qkv_w frags (bf16 hi)
__device__ __align__(16) uint2    g_pfrag[8 * 16 * 32];      // proj_w frags (bf16 hi)

// ---------------------------------------------------------------------------
// PTX helpers
// ---------------------------------------------------------------------------
__device__ __forceinline__ uint32_t smem_u32(const void* p) {
    uint32_t a;
    asm("{ .reg .u64 t; cvta.to.shared.u64 t, %1; cvt.u32.u64 %0, t; }" : "=r"(a) : "l"(p));
    return a;
}
__device__ __forceinline__ void ldsm4(uint32_t* f, uint32_t addr) {
    asm volatile("ldmatrix.sync.aligned.m8n8.x4.shared.b16 {%0,%1,%2,%3}, [%4];"
        : "=r"(f[0]), "=r"(f[1]), "=r"(f[2]), "=r"(f[3]) : "r"(addr));
}
__device__ __forceinline__ void cpasync16(uint32_t dst, const void* src) {
    asm volatile("cp.async.cg.shared.global [%0], [%1], 16;" :: "r"(dst), "l"(src));
}
#define CP_COMMIT() asm volatile("cp.async.commit_group;" ::: "memory")
#define CP_WAIT(n)  asm volatile("cp.async.wait_group %0;" :: "n"(n) : "memory")

// warp mma: D(16x8,f32) += A(16x16 bf16,row) * B(16x8 bf16,col)
__device__ __forceinline__ void mma16816(float* d, const uint32_t* a, const uint32_t* b) {
    asm volatile(
        "mma.sync.aligned.m16n8k16.row.col.f32.bf16.bf16.f32 "
        "{%0,%1,%2,%3}, {%4,%5,%6,%7}, {%8,%9}, {%0,%1,%2,%3};"
        : "+f"(d[0]), "+f"(d[1]), "+f"(d[2]), "+f"(d[3])
        : "r"(a[0]), "r"(a[1]), "r"(a[2]), "r"(a[3]), "r"(b[0]), "r"(b[1]));
}

// convert 8 fp32 -> 8 bf16, packed as uint4
__device__ __forceinline__ uint4 pack8(const float* v) {
    uint32_t h[4];
    #pragma unroll
    for (int i = 0; i < 4; i++) {
        __nv_bfloat16 h0 = __float2bfloat16_rn(v[2 * i]);
        __nv_bfloat16 h1 = __float2bfloat16_rn(v[2 * i + 1]);
        h[i] = (uint32_t)__bfloat16_as_ushort(h0) | ((uint32_t)__bfloat16_as_ushort(h1) << 16);
    }
    return make_uint4(h[0], h[1], h[2], h[3]);
}

// pack float2 -> bf16x2
__device__ __forceinline__ uint32_t packbf2(float a, float b) {
    __nv_bfloat16 h0 = __float2bfloat16_rn(a);
    __nv_bfloat16 h1 = __float2bfloat16_rn(b);
    return (uint32_t)__bfloat16_as_ushort(h0) | ((uint32_t)__bfloat16_as_ushort(h1) << 16);
}

// A tile geometry: bf16 [row][k], row stride 136 elems (272 B)
#define RSTRIDE 272
#define B_CHUNK 32768              // one N-chunk of fragments (4096 uint2)
#define SM_LNQKV (34816 + 2 * B_CHUNK)   // A + double-buffered B = 100352
#define SM_PROJ  67584             // max(A tile 34816, ts 128*132*4)

// ---------------------------------------------------------------------------
// Kernel 0: pre-fragment weights (bf16 hi) into per-lane LDG layout.
// lane holds n = nt*8 + (lane>>2), k = ks*16 + (lane&3)*2 (+1, +8, +9).
// ---------------------------------------------------------------------------
__global__ void prep_kernel(const float* __restrict__ qw, const float* __restrict__ pw) {
    int t = blockIdx.x * 256 + threadIdx.x;
    int lane = t & 31, nt = (t >> 5) & 15, ks = (t >> 9) & 7, chunk = t >> 12;
    int n = nt * 8 + (lane >> 2);
    int kb = ks * 16 + (lane & 3) * 2;
    if (t < 3 * 8 * 16 * 32) {
        const float* wr = qw + (chunk * 128 + n) * 128;
        float2 a = __ldg((const float2*)(wr + kb));
        float2 b = __ldg((const float2*)(wr + kb + 8));
        g_wfrag[t] = make_uint2(packbf2(a.x, a.y), packbf2(b.x, b.y));
    }
    if (t < 8 * 16 * 32) {
        const float* wr = pw + n * 128;
        float2 a = __ldg((const float2*)(wr + kb));
        float2 b = __ldg((const float2*)(wr + kb + 8));
        g_pfrag[t] = make_uint2(packbf2(a.x, a.y), packbf2(b.x, b.y));
    }
}

// ---------------------------------------------------------------------------
// Kernel 1: LN + QKV GEMM (single bf16), B staged in smem via cp.async
// (prefetch hidden under LayerNorm).  CTA = 128 voxels, 256 thr, 2 CTA/SM.
// smem: A [0,34816) | B0 [34816,67584) | B1 [67584,100352)
// ---------------------------------------------------------------------------
__global__ void __launch_bounds__(256, 2) lnqkv_mma(
    const float* __restrict__ x, const float* __restrict__ gam,
    const float* __restrict__ bet, const float* __restrict__ qb)
{
    extern __shared__ char smem[];
    const int tid = threadIdx.x, lane = tid & 31, wid = tid >> 5;
    const int vb = blockIdx.x * 128;
    const uint32_t sb = smem_u32(smem);

    // prefetch B chunk 0 into buffer 0
    #pragma unroll
    for (int t = 0; t < 8; t++) {
        int idx = tid + t * 256;               // 2048 x 16B = 32KB
        cpasync16(sb + 34816 + idx * 16, (const char*)g_wfrag + idx * 16);
    }
    CP_COMMIT();

    // ---- LayerNorm: 4 threads/voxel, 2 passes of 64 voxels ----
    #pragma unroll
    for (int vp = 0; vp < 2; vp++) {
        const int v = vp * 64 + (tid >> 2), q = tid & 3;
        float r[32];
        const float* xp = x + (q * 32) * NVOX + vb + v;
        #pragma unroll 8
        for (int i = 0; i < 32; i++) r[i] = xp[i * NVOX];
        float s = 0.f, s2 = 0.f;
        #pragma unroll
        for (int i = 0; i < 32; i++) { s += r[i]; s2 += r[i] * r[i]; }
        s  += __shfl_xor_sync(0xffffffffu, s, 1);  s  += __shfl_xor_sync(0xffffffffu, s, 2);
        s2 += __shfl_xor_sync(0xffffffffu, s2, 1); s2 += __shfl_xor_sync(0xffffffffu, s2, 2);
        float mu = s * (1.f / 128.f);
        float var = s2 * (1.f / 128.f) - mu * mu;
        float rs = rsqrtf(var + 1e-5f);
        #pragma unroll 8
        for (int i = 0; i < 32; i++) {
            int c = q * 32 + i;
            r[i] = (r[i] - mu) * rs * __ldg(&gam[c]) + __ldg(&bet[c]);
        }
        #pragma unroll
        for (int jj = 0; jj < 4; jj++) {
            int chunk = q * 4 + jj;
            *(uint4*)(smem + v * RSTRIDE + chunk * 16) = pack8(&r[8 * jj]);
        }
    }

    const int g = lane >> 2, t2 = lane & 3;
    const int m0 = (wid & 3) * 32, nhalf = wid >> 2, n0 = nhalf * 64;
    const uint32_t aA = sb + (m0 + (lane & 15)) * RSTRIDE + (lane >> 4) * 16;
    const int bidx = (nhalf * 256 + lane) * 8;   // byte offset of this lane's frag base

    #pragma unroll
    for (int nc = 0; nc < 3; nc++) {
        if (nc < 2) {                            // prefetch next chunk into other buffer
            uint32_t boff = 34816 + ((nc + 1) & 1) * B_CHUNK;
            #pragma unroll
            for (int t = 0; t < 8; t++) {
                int idx = tid + t * 256;
                cpasync16(sb + boff + idx * 16,
                          (const char*)g_wfrag + (nc + 1) * B_CHUNK + idx * 16);
            }
            CP_COMMIT();
            CP_WAIT(1);
        } else {
            CP_WAIT(0);
        }
        __syncthreads();                         // current buffer + A visible

        const char* bbase = smem + 34816 + (nc & 1) * B_CHUNK + bidx;

        float acc[2][8][4];
        #pragma unroll
        for (int nt = 0; nt < 8; nt++) {
            float b0 = __ldg(&qb[nc * 128 + n0 + nt * 8 + t2 * 2]);
            float b1 = __ldg(&qb[nc * 128 + n0 + nt * 8 + t2 * 2 + 1]);
            acc[0][nt][0] = b0; acc[0][nt][1] = b1; acc[0][nt][2] = b0; acc[0][nt][3] = b1;
            acc[1][nt][0] = b0; acc[1][nt][1] = b1; acc[1][nt][2] = b0; acc[1][nt][3] = b1;
        }

        #pragma unroll
        for (int ks = 0; ks < 8; ks++) {
            uint2 B[8];
            #pragma unroll
            for (int nt = 0; nt < 8; nt++)
                B[nt] = *(const uint2*)(bbase + (ks * 512 + nt * 32) * 8);
            uint32_t Ah[2][4];
            ldsm4(Ah[0], aA + ks * 32);
            ldsm4(Ah[1], aA + 16 * RSTRIDE + ks * 32);
            #pragma unroll
            for (int nt = 0; nt < 8; nt++) {
                uint32_t bh[2] = { B[nt].x, B[nt].y };
                mma16816(acc[0][nt], Ah[0], bh);
                mma16816(acc[1][nt], Ah[1], bh);
            }
        }

        // epilogue: fp16 outputs
        #pragma unroll
        for (int mt = 0; mt < 2; mt++) {
            int row = vb + m0 + mt * 16 + g;
            #pragma unroll
            for (int nt = 0; nt < 8; nt++) {
                int col = n0 + nt * 8 + t2 * 2;
                __half2 h0 = __floats2half2_rn(acc[mt][nt][0], acc[mt][nt][1]);
                __half2 h1 = __floats2half2_rn(acc[mt][nt][2], acc[mt][nt][3]);
                if (nc == 0) {
                    ((uint32_t*)g_qh)[row * 64 + (col >> 1)]       = *(uint32_t*)&h0;
                    ((uint32_t*)g_qh)[(row + 8) * 64 + (col >> 1)] = *(uint32_t*)&h1;
                } else {
                    int base = (nc == 1) ? 0 : 64;
                    ((uint32_t*)g_kv)[row * 128 + base + (col >> 1)]       = *(uint32_t*)&h0;
                    ((uint32_t*)g_kv)[(row + 8) * 128 + base + (col >> 1)] = *(uint32_t*)&h1;
                }
            }
        }
        if (nc < 2) __syncthreads();     // done reading buf[nc&1] before overwrite
    }
}

// ---------------------------------------------------------------------------
// Kernel 2: 27-neighbor attention, fp16 K/V/Q, single-phase halo, HFMA2.
// Block = 4x4x4 spatial tile x 4 heads, 256 threads, 2 blocks/SM.
// ---------------------------------------------------------------------------
__global__ void __launch_bounds__(256, 2) attn_kernel() {
    extern __shared__ char smem[];
    char* ksm = smem;
    char* vsm = smem + 55296;
    const int tid = threadIdx.x;
    const int b = blockIdx.x;
    const int tx = b >> 6, ty = (b >> 3) & 7, tz = b & 7;
    const int hx0 = tx * 4 - 1, hy0 = ty * 4 - 1, hz0 = tz * 4 - 1;

    const int j = tid & 63, h = tid >> 6;
    const int lx = j >> 4, ly = (j >> 2) & 3, lz = j & 3;
    const int gx = tx * 4 + lx, gy = ty * 4 + ly, gz = tz * 4 + lz;
    const int gv0 = (gx << 10) + (gy << 5) + gz;

    // halo load: 216 positions x 512B (K 256 + V 256), 16B chunks, swizzled
    for (int i = tid; i < 216 * 32; i += 256) {
        int p = i >> 5, c = i & 31;
        int hx = p / 36, r = p - hx * 36, hy = r / 6, hz = r - hy * 6;
        int ggx = min(max(hx0 + hx, 0), 31);
        int ggy = min(max(hy0 + hy, 0), 31);
        int ggz = min(max(hz0 + hz, 0), 31);
        int gv = (ggx << 10) + (ggy << 5) + ggz;
        uint4 t = __ldg((const uint4*)((const char*)g_kv + gv * 512 + c * 16));
        char* base = (c < 16) ? ksm : vsm;
        int cc = c & 15;
        *(uint4*)(base + p * 256 + ((cc ^ (p & 15)) << 4)) = t;
    }

    // q -> half2, pre-scaled
    __half2 qh[16];
    {
        const __half2 s2 = __float2half2_rn(SCALE);
        const uint4* qp = (const uint4*)&g_qh[gv0 * 128 + h * 32];
        #pragma unroll
        for (int c = 0; c < 4; c++) {
            uint4 t = __ldg(qp + c);
            const __half2* q2 = (const __half2*)&t;
            qh[c * 4 + 0] = __hmul2(q2[0], s2);
            qh[c * 4 + 1] = __hmul2(q2[1], s2);
            qh[c * 4 + 2] = __hmul2(q2[2], s2);
            qh[c * 4 + 3] = __hmul2(q2[3], s2);
        }
    }
    __syncthreads();

    const int sx = min(max(gx - 1, 0), 29) - hx0;
    const int sy = min(max(gy - 1, 0), 29) - hy0;
    const int sz = min(max(gz - 1, 0), 29) - hz0;

    const __half2 z2 = __float2half2_rn(0.f);
    float sc[27];
    #pragma unroll
    for (int dx = 0; dx < 3; dx++)
    #pragma unroll
    for (int dy = 0; dy < 3; dy++)
    #pragma unroll
    for (int dz = 0; dz < 3; dz++) {
        int p = (sx + dx) * 36 + (sy + dy) * 6 + (sz + dz);
        const char* kb = ksm + p * 256;
        int psw = p & 15;
        __half2 a0 = z2, a1 = z2, a2 = z2, a3 = z2;
        #pragma unroll
        for (int cc = 0; cc < 4; cc++) {
            uint4 t = *(const uint4*)(kb + (((h * 4 + cc) ^ psw) << 4));
            const __half2* kk = (const __half2*)&t;
            a0 = __hfma2(qh[cc * 4 + 0], kk[0], a0);
            a1 = __hfma2(qh[cc * 4 + 1], kk[1], a1);
            a2 = __hfma2(qh[cc * 4 + 2], kk[2], a2);
            a3 = __hfma2(qh[cc * 4 + 3], kk[3], a3);
        }
        __half2 as = __hadd2(__hadd2(a0, a1), __hadd2(a2, a3));
        float2 f = __half22float2(as);
        sc[dx * 9 + dy * 3 + dz] = f.x + f.y;
    }

    // softmax (fp32)
    float mx = sc[0];
    #pragma unroll
    for (int n = 1; n < 27; n++) mx = fmaxf(mx, sc[n]);
    float sum = 0.f;
    #pragma unroll
    for (int n = 0; n < 27; n++) { float e = __expf(sc[n] - mx); sc[n] = e; sum += e; }
    float inv = __fdividef(1.f, sum);

    // weighted V sum (HFMA2)
    __half2 out[16];
    #pragma unroll
    for (int i = 0; i < 16; i++) out[i] = z2;

    #pragma unroll
    for (int dx = 0; dx < 3; dx++)
    #pragma unroll
    for (int dy = 0; dy < 3; dy++)
    #pragma unroll
    for (int dz = 0; dz < 3; dz++) {
        int p = (sx + dx) * 36 + (sy + dy) * 6 + (sz + dz);
        const char* vbp = vsm + p * 256;
        int psw = p & 15;
        __half2 wh = __float2half2_rn(sc[dx * 9 + dy * 3 + dz]);
        #pragma unroll
        for (int cc = 0; cc < 4; cc++) {
            uint4 t = *(const uint4*)(vbp + (((h * 4 + cc) ^ psw) << 4));
            const __half2* vv = (const __half2*)&t;
            out[cc * 4 + 0] = __hfma2(wh, vv[0], out[cc * 4 + 0]);
            out[cc * 4 + 1] = __hfma2(wh, vv[1], out[cc * 4 + 1]);
            out[cc * 4 + 2] = __hfma2(wh, vv[2], out[cc * 4 + 2]);
            out[cc * 4 + 3] = __hfma2(wh, vv[3], out[cc * 4 + 3]);
        }
    }

    // transpose through smem -> uint4 stores to g_ah[c2][v]
    __syncthreads();
    uint32_t* buf = (uint32_t*)ksm;          // [64 c2][64 j]
    #pragma unroll
    for (int c = 0; c < 16; c++) {
        float2 f = __half22float2(out[c]);
        __half2 o = __floats2half2_rn(f.x * inv, f.y * inv);
        buf[(h * 16 + c) * 64 + j] = *(uint32_t*)&o;
    }
    __syncthreads();
    for (int i = tid; i < 64 * 16; i += 256) {
        int c2 = i >> 4, r = i & 15;
        int vlx = r >> 2, vly = r & 3;
        uint4 t = *(const uint4*)&buf[c2 * 64 + vlx * 16 + vly * 4];
        *(uint4*)&g_ah[c2 * NVOX + (((tx * 4 + vlx) << 10) + ((ty * 4 + vly) << 5) + tz * 4)] = t;
    }
}

// ---------------------------------------------------------------------------
// Kernel 3: proj GEMM (single bf16, B from L2 via LDG) + bias + residual.
// 2 CTA/SM.
// ---------------------------------------------------------------------------
__global__ void __launch_bounds__(256, 2) proj_mma(
    const float* __restrict__ x, const float* __restrict__ pb, float* __restrict__ out)
{
    extern __shared__ char smem[];
    const int tid = threadIdx.x, lane = tid & 31, wid = tid >> 5;
    const int vb = blockIdx.x * 128;
    const uint32_t sb = smem_u32(smem);

    // A conversion: g_ah[c2][v] -> A hi tile, 4 thr/voxel, 2 passes
    #pragma unroll
    for (int vp = 0; vp < 2; vp++) {
        const int v = vp * 64 + (tid >> 2), q = tid & 3;
        float r[32];
        const uint32_t* ap = g_ah + (q * 16) * NVOX + vb + v;
        #pragma unroll 8
        for (int c2 = 0; c2 < 16; c2++) {
            uint32_t u = ap[c2 * NVOX];
            float2 f = __half22float2(*(const __half2*)&u);
            r[2 * c2] = f.x; r[2 * c2 + 1] = f.y;
        }
        #pragma unroll
        for (int jj = 0; jj < 4; jj++) {
            int chunk = q * 4 + jj;
            *(uint4*)(smem + v * RSTRIDE + chunk * 16) = pack8(&r[8 * jj]);
        }
    }
    __syncthreads();

    const int g = lane >> 2, t2 = lane & 3;
    const int m0 = (wid & 3) * 32, nhalf = wid >> 2, n0 = nhalf * 64;
    const uint32_t aA = sb + (m0 + (lane & 15)) * RSTRIDE + (lane >> 4) * 16;
    const uint2* __restrict__ bp = g_pfrag + nhalf * 256 + lane;

    float acc[2][8][4];
    #pragma unroll
    for (int nt = 0; nt < 8; nt++) {
        float b0 = __ldg(&pb[n0 + nt * 8 + t2 * 2]);
        float b1 = __ldg(&pb[n0 + nt * 8 + t2 * 2 + 1]);
        acc[0][nt][0] = b0; acc[0][nt][1] = b1; acc[0][nt][2] = b0; acc[0][nt][3] = b1;
        acc[1][nt][0] = b0; acc[1][nt][1] = b1; acc[1][nt][2] = b0; acc[1][nt][3] = b1;
    }

    #pragma unroll
    for (int ks = 0; ks < 8; ks++) {
        uint2 B[8];
        #pragma unroll
        for (int nt = 0; nt < 8; nt++)
            B[nt] = __ldg(bp + ks * 512 + nt * 32);
        uint32_t Ah[2][4];
        ldsm4(Ah[0], aA + ks * 32);
        ldsm4(Ah[1], aA + 16 * RSTRIDE + ks * 32);
        #pragma unroll
        for (int nt = 0; nt < 8; nt++) {
            uint32_t bh[2] = { B[nt].x, B[nt].y };
            mma16816(acc[0][nt], Ah[0], bh);
            mma16816(acc[1][nt], Ah[1], bh);
        }
    }

    // transpose D through smem: ts[c][v], stride 132
    __syncthreads();
    float* ts = (float*)smem;
    #pragma unroll
    for (int mt = 0; mt < 2; mt++) {
        int row = m0 + mt * 16 + g;
        #pragma unroll
        for (int nt = 0; nt < 8; nt++) {
            int col = n0 + nt * 8 + t2 * 2;
            ts[col * 132 + row]           = acc[mt][nt][0];
            ts[(col + 1) * 132 + row]     = acc[mt][nt][1];
            ts[col * 132 + row + 8]       = acc[mt][nt][2];
            ts[(col + 1) * 132 + row + 8] = acc[mt][nt][3];
        }
    }
    __syncthreads();

    // residual + coalesced channel-major stores
    for (int i = tid; i < 128 * 32; i += 256) {
        int c = i >> 5, vq = i & 31;
        int off = c * NVOX + vb + vq * 4;
        float4 t = *(const float4*)&ts[c * 132 + vq * 4];
        float4 xr = *(const float4*)&x[off];
        *(float4*)&out[off] = make_float4(t.x + xr.x, t.y + xr.y, t.z + xr.z, t.w + xr.w);
    }
}

// ---------------------------------------------------------------------------
extern "C" void kernel_launch(void* const* d_in, const int* in_sizes, int n_in,
                              void* d_out, int out_size)
{
    const float* x   = (const float*)d_in[0];
    const float* gam = (const float*)d_in[1];
    const float* bet = (const float*)d_in[2];
    const float* qw  = (const float*)d_in[3];
    const float* qb  = (const float*)d_in[4];
    const float* pw  = (const float*)d_in[5];
    const float* pb  = (const float*)d_in[6];
    float* out = (float*)d_out;

    const int SMEM_ATTN = 110592;

    cudaFuncSetAttribute(lnqkv_mma,   cudaFuncAttributeMaxDynamicSharedMemorySize, SM_LNQKV);
    cudaFuncSetAttribute(attn_kernel, cudaFuncAttributeMaxDynamicSharedMemorySize, SMEM_ATTN);
    cudaFuncSetAttribute(proj_mma,    cudaFuncAttributeMaxDynamicSharedMemorySize, SM_PROJ);

    prep_kernel<<<48, 256>>>(qw, pw);
    lnqkv_mma<<<256, 256, SM_LNQKV>>>(x, gam, bet, qb);
    attn_kernel<<<512, 256, SMEM_ATTN>>>();
    proj_mma<<<256, 256, SM_PROJ>>>(x, pb, out);
}

// round 15
// speedup vs baseline: 1.0695x; 1.0499x over previous
#include <cuda_runtime.h>
#include <cuda_fp16.h>
#include <cuda_bf16.h>
#include <cstdint>

#define NVOX 32768
#define SCALE 0.17677669529663689f   // 1/sqrt(32)

// Scratch (allocation-free: device globals)
__device__ __align__(16) __half   g_qh[NVOX * 128];   // [v][128] q, fp16
__device__ __align__(16) __half   g_kv[NVOX * 256];   // [v][ k:128 | v:128 ] fp16
__device__ __align__(16) uint4    g_abf[NVOX * 16];   // [v][128] attn out, bf16 (256B rows)
__device__ __align__(16) uint2    g_wfrag[3 * 8 * 16 * 32];  // qkv_w frags (bf16 hi)
__device__ __align__(16) uint2    g_pfrag[8 * 16 * 32];      // proj_w frags (bf16 hi)

// ---------------------------------------------------------------------------
// PTX helpers
// ---------------------------------------------------------------------------
__device__ __forceinline__ uint32_t smem_u32(const void* p) {
    uint32_t a;
    asm("{ .reg .u64 t; cvta.to.shared.u64 t, %1; cvt.u32.u64 %0, t; }" : "=r"(a) : "l"(p));
    return a;
}
__device__ __forceinline__ void ldsm4(uint32_t* f, uint32_t addr) {
    asm volatile("ldmatrix.sync.aligned.m8n8.x4.shared.b16 {%0,%1,%2,%3}, [%4];"
        : "=r"(f[0]), "=r"(f[1]), "=r"(f[2]), "=r"(f[3]) : "r"(addr));
}
__device__ __forceinline__ void cpasync16(uint32_t dst, const void* src) {
    asm volatile("cp.async.cg.shared.global [%0], [%1], 16;" :: "r"(dst), "l"(src));
}
#define CP_COMMIT() asm volatile("cp.async.commit_group;" ::: "memory")
#define CP_WAIT(n)  asm volatile("cp.async.wait_group %0;" :: "n"(n) : "memory")

// warp mma: D(16x8,f32) += A(16x16 bf16,row) * B(16x8 bf16,col)
__device__ __forceinline__ void mma16816(float* d, const uint32_t* a, const uint32_t* b) {
    asm volatile(
        "mma.sync.aligned.m16n8k16.row.col.f32.bf16.bf16.f32 "
        "{%0,%1,%2,%3}, {%4,%5,%6,%7}, {%8,%9}, {%0,%1,%2,%3};"
        : "+f"(d[0]), "+f"(d[1]), "+f"(d[2]), "+f"(d[3])
        : "r"(a[0]), "r"(a[1]), "r"(a[2]), "r"(a[3]), "r"(b[0]), "r"(b[1]));
}

// convert 8 fp32 -> 8 bf16, packed as uint4
__device__ __forceinline__ uint4 pack8(const float* v) {
    uint32_t h[4];
    #pragma unroll
    for (int i = 0; i < 4; i++) {
        __nv_bfloat16 h0 = __float2bfloat16_rn(v[2 * i]);
        __nv_bfloat16 h1 = __float2bfloat16_rn(v[2 * i + 1]);
        h[i] = (uint32_t)__bfloat16_as_ushort(h0) | ((uint32_t)__bfloat16_as_ushort(h1) << 16);
    }
    return make_uint4(h[0], h[1], h[2], h[3]);
}

// pack float2 -> bf16x2
__device__ __forceinline__ uint32_t packbf2(float a, float b) {
    __nv_bfloat16 h0 = __float2bfloat16_rn(a);
    __nv_bfloat16 h1 = __float2bfloat16_rn(b);
    return (uint32_t)__bfloat16_as_ushort(h0) | ((uint32_t)__bfloat16_as_ushort(h1) << 16);
}

// A tile geometry: bf16 [row][k], row stride 136 elems (272 B)
#define RSTRIDE 272
#define B_CHUNK 32768              // one N-chunk of fragments (4096 uint2)
#define SM_LNQKV (34816 + 2 * B_CHUNK)   // A + double-buffered B = 100352
#define SM_PROJ  67584             // max(A tile 34816, ts 128*132*4)

// ---------------------------------------------------------------------------
// Kernel 0: pre-fragment weights (bf16 hi) into per-lane LDG layout.
// lane holds n = nt*8 + (lane>>2), k = ks*16 + (lane&3)*2 (+1, +8, +9).
// ---------------------------------------------------------------------------
__global__ void prep_kernel(const float* __restrict__ qw, const float* __restrict__ pw) {
    int t = blockIdx.x * 256 + threadIdx.x;
    int lane = t & 31, nt = (t >> 5) & 15, ks = (t >> 9) & 7, chunk = t >> 12;
    int n = nt * 8 + (lane >> 2);
    int kb = ks * 16 + (lane & 3) * 2;
    if (t < 3 * 8 * 16 * 32) {
        const float* wr = qw + (chunk * 128 + n) * 128;
        float2 a = __ldg((const float2*)(wr + kb));
        float2 b = __ldg((const float2*)(wr + kb + 8));
        g_wfrag[t] = make_uint2(packbf2(a.x, a.y), packbf2(b.x, b.y));
    }
    if (t < 8 * 16 * 32) {
        const float* wr = pw + n * 128;
        float2 a = __ldg((const float2*)(wr + kb));
        float2 b = __ldg((const float2*)(wr + kb + 8));
        g_pfrag[t] = make_uint2(packbf2(a.x, a.y), packbf2(b.x, b.y));
    }
}

// ---------------------------------------------------------------------------
// Kernel 1: LN + QKV GEMM (single bf16), B staged in smem via cp.async
// (prefetch hidden under LayerNorm).  CTA = 128 voxels, 256 thr, 2 CTA/SM.
// smem: A [0,34816) | B0 [34816,67584) | B1 [67584,100352)
// ---------------------------------------------------------------------------
__global__ void __launch_bounds__(256, 2) lnqkv_mma(
    const float* __restrict__ x, const float* __restrict__ gam,
    const float* __restrict__ bet, const float* __restrict__ qb)
{
    extern __shared__ char smem[];
    const int tid = threadIdx.x, lane = tid & 31, wid = tid >> 5;
    const int vb = blockIdx.x * 128;
    const uint32_t sb = smem_u32(smem);

    // prefetch B chunk 0 into buffer 0
    #pragma unroll
    for (int t = 0; t < 8; t++) {
        int idx = tid + t * 256;               // 2048 x 16B = 32KB
        cpasync16(sb + 34816 + idx * 16, (const char*)g_wfrag + idx * 16);
    }
    CP_COMMIT();

    // ---- LayerNorm: 4 threads/voxel, 2 passes of 64 voxels ----
    #pragma unroll
    for (int vp = 0; vp < 2; vp++) {
        const int v = vp * 64 + (tid >> 2), q = tid & 3;
        float r[32];
        const float* xp = x + (q * 32) * NVOX + vb + v;
        #pragma unroll 8
        for (int i = 0; i < 32; i++) r[i] = xp[i * NVOX];
        float s = 0.f, s2 = 0.f;
        #pragma unroll
        for (int i = 0; i < 32; i++) { s += r[i]; s2 += r[i] * r[i]; }
        s  += __shfl_xor_sync(0xffffffffu, s, 1);  s  += __shfl_xor_sync(0xffffffffu, s, 2);
        s2 += __shfl_xor_sync(0xffffffffu, s2, 1); s2 += __shfl_xor_sync(0xffffffffu, s2, 2);
        float mu = s * (1.f / 128.f);
        float var = s2 * (1.f / 128.f) - mu * mu;
        float rs = rsqrtf(var + 1e-5f);
        #pragma unroll 8
        for (int i = 0; i < 32; i++) {
            int c = q * 32 + i;
            r[i] = (r[i] - mu) * rs * __ldg(&gam[c]) + __ldg(&bet[c]);
        }
        #pragma unroll
        for (int jj = 0; jj < 4; jj++) {
            int chunk = q * 4 + jj;
            *(uint4*)(smem + v * RSTRIDE + chunk * 16) = pack8(&r[8 * jj]);
        }
    }

    const int g = lane >> 2, t2 = lane & 3;
    const int m0 = (wid & 3) * 32, nhalf = wid >> 2, n0 = nhalf * 64;
    const uint32_t aA = sb + (m0 + (lane & 15)) * RSTRIDE + (lane >> 4) * 16;
    const int bidx = (nhalf * 256 + lane) * 8;   // byte offset of this lane's frag base

    #pragma unroll
    for (int nc = 0; nc < 3; nc++) {
        if (nc < 2) {                            // prefetch next chunk into other buffer
            uint32_t boff = 34816 + ((nc + 1) & 1) * B_CHUNK;
            #pragma unroll
            for (int t = 0; t < 8; t++) {
                int idx = tid + t * 256;
                cpasync16(sb + boff + idx * 16,
                          (const char*)g_wfrag + (nc + 1) * B_CHUNK + idx * 16);
            }
            CP_COMMIT();
            CP_WAIT(1);
        } else {
            CP_WAIT(0);
        }
        __syncthreads();                         // current buffer + A visible

        const char* bbase = smem + 34816 + (nc & 1) * B_CHUNK + bidx;

        float acc[2][8][4];
        #pragma unroll
        for (int nt = 0; nt < 8; nt++) {
            float b0 = __ldg(&qb[nc * 128 + n0 + nt * 8 + t2 * 2]);
            float b1 = __ldg(&qb[nc * 128 + n0 + nt * 8 + t2 * 2 + 1]);
            acc[0][nt][0] = b0; acc[0][nt][1] = b1; acc[0][nt][2] = b0; acc[0][nt][3] = b1;
            acc[1][nt][0] = b0; acc[1][nt][1] = b1; acc[1][nt][2] = b0; acc[1][nt][3] = b1;
        }

        #pragma unroll
        for (int ks = 0; ks < 8; ks++) {
            uint2 B[8];
            #pragma unroll
            for (int nt = 0; nt < 8; nt++)
                B[nt] = *(const uint2*)(bbase + (ks * 512 + nt * 32) * 8);
            uint32_t Ah[2][4];
            ldsm4(Ah[0], aA + ks * 32);
            ldsm4(Ah[1], aA + 16 * RSTRIDE + ks * 32);
            #pragma unroll
            for (int nt = 0; nt < 8; nt++) {
                uint32_t bh[2] = { B[nt].x, B[nt].y };
                mma16816(acc[0][nt], Ah[0], bh);
                mma16816(acc[1][nt], Ah[1], bh);
            }
        }

        // epilogue: fp16 outputs
        #pragma unroll
        for (int mt = 0; mt < 2; mt++) {
            int row = vb + m0 + mt * 16 + g;
            #pragma unroll
            for (int nt = 0; nt < 8; nt++) {
                int col = n0 + nt * 8 + t2 * 2;
                __half2 h0 = __floats2half2_rn(acc[mt][nt][0], acc[mt][nt][1]);
                __half2 h1 = __floats2half2_rn(acc[mt][nt][2], acc[mt][nt][3]);
                if (nc == 0) {
                    ((uint32_t*)g_qh)[row * 64 + (col >> 1)]       = *(uint32_t*)&h0;
                    ((uint32_t*)g_qh)[(row + 8) * 64 + (col >> 1)] = *(uint32_t*)&h1;
                } else {
                    int base = (nc == 1) ? 0 : 64;
                    ((uint32_t*)g_kv)[row * 128 + base + (col >> 1)]       = *(uint32_t*)&h0;
                    ((uint32_t*)g_kv)[(row + 8) * 128 + base + (col >> 1)] = *(uint32_t*)&h1;
                }
            }
        }
        if (nc < 2) __syncthreads();     // done reading buf[nc&1] before overwrite
    }
}

// ---------------------------------------------------------------------------
// Kernel 2: 27-neighbor attention, fp16 K/V/Q, single-phase halo, HFMA2.
// Output: bf16 voxel-major g_abf[v][128].
// Block = 4x4x4 spatial tile x 4 heads, 256 threads, 2 blocks/SM.
// ---------------------------------------------------------------------------
__global__ void __launch_bounds__(256, 2) attn_kernel() {
    extern __shared__ char smem[];
    char* ksm = smem;
    char* vsm = smem + 55296;
    const int tid = threadIdx.x;
    const int b = blockIdx.x;
    const int tx = b >> 6, ty = (b >> 3) & 7, tz = b & 7;
    const int hx0 = tx * 4 - 1, hy0 = ty * 4 - 1, hz0 = tz * 4 - 1;

    const int j = tid & 63, h = tid >> 6;
    const int lx = j >> 4, ly = (j >> 2) & 3, lz = j & 3;
    const int gx = tx * 4 + lx, gy = ty * 4 + ly, gz = tz * 4 + lz;
    const int gv0 = (gx << 10) + (gy << 5) + gz;

    // halo load: 216 positions x 512B (K 256 + V 256), 16B chunks, swizzled
    for (int i = tid; i < 216 * 32; i += 256) {
        int p = i >> 5, c = i & 31;
        int hx = p / 36, r = p - hx * 36, hy = r / 6, hz = r - hy * 6;
        int ggx = min(max(hx0 + hx, 0), 31);
        int ggy = min(max(hy0 + hy, 0), 31);
        int ggz = min(max(hz0 + hz, 0), 31);
        int gv = (ggx << 10) + (ggy << 5) + ggz;
        uint4 t = __ldg((const uint4*)((const char*)g_kv + gv * 512 + c * 16));
        char* base = (c < 16) ? ksm : vsm;
        int cc = c & 15;
        *(uint4*)(base + p * 256 + ((cc ^ (p & 15)) << 4)) = t;
    }

    // q -> half2, pre-scaled
    __half2 qh[16];
    {
        const __half2 s2 = __float2half2_rn(SCALE);
        const uint4* qp = (const uint4*)&g_qh[gv0 * 128 + h * 32];
        #pragma unroll
        for (int c = 0; c < 4; c++) {
            uint4 t = __ldg(qp + c);
            const __half2* q2 = (const __half2*)&t;
            qh[c * 4 + 0] = __hmul2(q2[0], s2);
            qh[c * 4 + 1] = __hmul2(q2[1], s2);
            qh[c * 4 + 2] = __hmul2(q2[2], s2);
            qh[c * 4 + 3] = __hmul2(q2[3], s2);
        }
    }
    __syncthreads();

    const int sx = min(max(gx - 1, 0), 29) - hx0;
    const int sy = min(max(gy - 1, 0), 29) - hy0;
    const int sz = min(max(gz - 1, 0), 29) - hz0;

    const __half2 z2 = __float2half2_rn(0.f);
    float sc[27];
    #pragma unroll
    for (int dx = 0; dx < 3; dx++)
    #pragma unroll
    for (int dy = 0; dy < 3; dy++)
    #pragma unroll
    for (int dz = 0; dz < 3; dz++) {
        int p = (sx + dx) * 36 + (sy + dy) * 6 + (sz + dz);
        const char* kb = ksm + p * 256;
        int psw = p & 15;
        __half2 a0 = z2, a1 = z2, a2 = z2, a3 = z2;
        #pragma unroll
        for (int cc = 0; cc < 4; cc++) {
            uint4 t = *(const uint4*)(kb + (((h * 4 + cc) ^ psw) << 4));
            const __half2* kk = (const __half2*)&t;
            a0 = __hfma2(qh[cc * 4 + 0], kk[0], a0);
            a1 = __hfma2(qh[cc * 4 + 1], kk[1], a1);
            a2 = __hfma2(qh[cc * 4 + 2], kk[2], a2);
            a3 = __hfma2(qh[cc * 4 + 3], kk[3], a3);
        }
        __half2 as = __hadd2(__hadd2(a0, a1), __hadd2(a2, a3));
        float2 f = __half22float2(as);
        sc[dx * 9 + dy * 3 + dz] = f.x + f.y;
    }

    // softmax (fp32)
    float mx = sc[0];
    #pragma unroll
    for (int n = 1; n < 27; n++) mx = fmaxf(mx, sc[n]);
    float sum = 0.f;
    #pragma unroll
    for (int n = 0; n < 27; n++) { float e = __expf(sc[n] - mx); sc[n] = e; sum += e; }
    float inv = __fdividef(1.f, sum);

    // weighted V sum (HFMA2)
    __half2 out[16];
    #pragma unroll
    for (int i = 0; i < 16; i++) out[i] = z2;

    #pragma unroll
    for (int dx = 0; dx < 3; dx++)
    #pragma unroll
    for (int dy = 0; dy < 3; dy++)
    #pragma unroll
    for (int dz = 0; dz < 3; dz++) {
        int p = (sx + dx) * 36 + (sy + dy) * 6 + (sz + dz);
        const char* vbp = vsm + p * 256;
        int psw = p & 15;
        __half2 wh = __float2half2_rn(sc[dx * 9 + dy * 3 + dz]);
        #pragma unroll
        for (int cc = 0; cc < 4; cc++) {
            uint4 t = *(const uint4*)(vbp + (((h * 4 + cc) ^ psw) << 4));
            const __half2* vv = (const __half2*)&t;
            out[cc * 4 + 0] = __hfma2(wh, vv[0], out[cc * 4 + 0]);
            out[cc * 4 + 1] = __hfma2(wh, vv[1], out[cc * 4 + 1]);
            out[cc * 4 + 2] = __hfma2(wh, vv[2], out[cc * 4 + 2]);
            out[cc * 4 + 3] = __hfma2(wh, vv[3], out[cc * 4 + 3]);
        }
    }

    // transpose to voxel-major bf16 rows via smem buf [64v][68 words]
    __syncthreads();
    uint32_t* buf = (uint32_t*)ksm;
    #pragma unroll
    for (int c = 0; c < 16; c++) {
        float2 f = __half22float2(out[c]);
        buf[j * 68 + h * 16 + c] = packbf2(f.x * inv, f.y * inv);
    }
    __syncthreads();
    // copy out: 64 rows x 256B; z-runs of 4 voxels are 1KB contiguous
    for (int i = tid; i < 64 * 16; i += 256) {
        int v = i >> 4, ch = i & 15;
        uint4 t = *(const uint4*)&buf[v * 68 + ch * 4];
        int vlx = v >> 4, vly = (v >> 2) & 3, vlz = v & 3;
        int gv = (((tx * 4 + vlx) << 10) + ((ty * 4 + vly) << 5) + tz * 4 + vlz);
        g_abf[gv * 16 + ch] = t;
    }
}

// ---------------------------------------------------------------------------
// Kernel 3: proj GEMM (single bf16, B from L2 via LDG) + bias + residual.
// A tile loaded directly from g_abf via cp.async (no conversion).  2 CTA/SM.
// ---------------------------------------------------------------------------
__global__ void __launch_bounds__(256, 2) proj_mma(
    const float* __restrict__ x, const float* __restrict__ pb, float* __restrict__ out)
{
    extern __shared__ char smem[];
    const int tid = threadIdx.x, lane = tid & 31, wid = tid >> 5;
    const int vb = blockIdx.x * 128;
    const uint32_t sb = smem_u32(smem);

    // A tile: straight async copy of 128 x 256B bf16 rows into stride-272 tile
    {
        const char* src = (const char*)g_abf + (size_t)vb * 256;
        #pragma unroll
        for (int t = 0; t < 8; t++) {
            int idx = tid + t * 256;            // 2048 chunks of 16B
            int v = idx >> 4, ch = idx & 15;
            cpasync16(sb + v * RSTRIDE + ch * 16, src + idx * 16);
        }
        CP_COMMIT();
        CP_WAIT(0);
    }
    __syncthreads();

    const int g = lane >> 2, t2 = lane & 3;
    const int m0 = (wid & 3) * 32, nhalf = wid >> 2, n0 = nhalf * 64;
    const uint32_t aA = sb + (m0 + (lane & 15)) * RSTRIDE + (lane >> 4) * 16;
    const uint2* __restrict__ bp = g_pfrag + nhalf * 256 + lane;

    float acc[2][8][4];
    #pragma unroll
    for (int nt = 0; nt < 8; nt++) {
        float b0 = __ldg(&pb[n0 + nt * 8 + t2 * 2]);
        float b1 = __ldg(&pb[n0 + nt * 8 + t2 * 2 + 1]);
        acc[0][nt][0] = b0; acc[0][nt][1] = b1; acc[0][nt][2] = b0; acc[0][nt][3] = b1;
        acc[1][nt][0] = b0; acc[1][nt][1] = b1; acc[1][nt][2] = b0; acc[1][nt][3] = b1;
    }

    #pragma unroll
    for (int ks = 0; ks < 8; ks++) {
        uint2 B[8];
        #pragma unroll
        for (int nt = 0; nt < 8; nt++)
            B[nt] = __ldg(bp + ks * 512 + nt * 32);
        uint32_t Ah[2][4];
        ldsm4(Ah[0], aA + ks * 32);
        ldsm4(Ah[1], aA + 16 * RSTRIDE + ks * 32);
        #pragma unroll
        for (int nt = 0; nt < 8; nt++) {
            uint32_t bh[2] = { B[nt].x, B[nt].y };
            mma16816(acc[0][nt], Ah[0], bh);
            mma16816(acc[1][nt], Ah[1], bh);
        }
    }

    // transpose D through smem: ts[c][v], stride 132
    __syncthreads();
    float* ts = (float*)smem;
    #pragma unroll
    for (int mt = 0; mt < 2; mt++) {
        int row = m0 + mt * 16 + g;
        #pragma unroll
        for (int nt = 0; nt < 8; nt++) {
            int col = n0 + nt * 8 + t2 * 2;
            ts[col * 132 + row]           = acc[mt][nt][0];
            ts[(col + 1) * 132 + row]     = acc[mt][nt][1];
            ts[col * 132 + row + 8]       = acc[mt][nt][2];
            ts[(col + 1) * 132 + row + 8] = acc[mt][nt][3];
        }
    }
    __syncthreads();

    // residual + coalesced channel-major stores
    for (int i = tid; i < 128 * 32; i += 256) {
        int c = i >> 5, vq = i & 31;
        int off = c * NVOX + vb + vq * 4;
        float4 t = *(const float4*)&ts[c * 132 + vq * 4];
        float4 xr = *(const float4*)&x[off];
        *(float4*)&out[off] = make_float4(t.x + xr.x, t.y + xr.y, t.z + xr.z, t.w + xr.w);
    }
}

// ---------------------------------------------------------------------------
extern "C" void kernel_launch(void* const* d_in, const int* in_sizes, int n_in,
                              void* d_out, int out_size)
{
    const float* x   = (const float*)d_in[0];
    const float* gam = (const float*)d_in[1];
    const float* bet = (const float*)d_in[2];
    const float* qw  = (const float*)d_in[3];
    const float* qb  = (const float*)d_in[4];
    const float* pw  = (const float*)d_in[5];
    const float* pb  = (const float*)d_in[6];
    float* out = (float*)d_out;

    const int SMEM_ATTN = 110592;

    cudaFuncSetAttribute(lnqkv_mma,   cudaFuncAttributeMaxDynamicSharedMemorySize, SM_LNQKV);
    cudaFuncSetAttribute(attn_kernel, cudaFuncAttributeMaxDynamicSharedMemorySize, SMEM_ATTN);
    cudaFuncSetAttribute(proj_mma,    cudaFuncAttributeMaxDynamicSharedMemorySize, SM_PROJ);

    prep_kernel<<<48, 256>>>(qw, pw);
    lnqkv_mma<<<256, 256, SM_LNQKV>>>(x, gam, bet, qb);
    attn_kernel<<<512, 256, SMEM_ATTN>>>();
    proj_mma<<<256, 256, SM_PROJ>>>(x, pb, out);
}

// round 16
// speedup vs baseline: 1.0984x; 1.0270x over previous
#include <cuda_runtime.h>
#include <cuda_fp16.h>
#include <cuda_bf16.h>
#include <cstdint>

#define NVOX 32768
#define SCALE 0.17677669529663689f   // 1/sqrt(32)

// Scratch (allocation-free: device globals)
__device__ __align__(16) __half   g_qh[NVOX * 128];   // [v][128] q, fp16
__device__ __align__(16) __half   g_kv[NVOX * 256];   // [v][ k:128 | v:128 ] fp16
__device__ __align__(16) uint4    g_abf[NVOX * 16];   // [v][128] attn out, bf16 (256B rows)
__device__ __align__(16) uint2    g_wfrag[3 * 8 * 16 * 32];  // qkv_w frags (bf16 hi)
__device__ __align__(16) uint2    g_pfrag[8 * 16 * 32];      // proj_w frags (bf16 hi)

// ---------------------------------------------------------------------------
// PTX helpers
// ---------------------------------------------------------------------------
__device__ __forceinline__ uint32_t smem_u32(const void* p) {
    uint32_t a;
    asm("{ .reg .u64 t; cvta.to.shared.u64 t, %1; cvt.u32.u64 %0, t; }" : "=r"(a) : "l"(p));
    return a;
}
__device__ __forceinline__ void ldsm4(uint32_t* f, uint32_t addr) {
    asm volatile("ldmatrix.sync.aligned.m8n8.x4.shared.b16 {%0,%1,%2,%3}, [%4];"
        : "=r"(f[0]), "=r"(f[1]), "=r"(f[2]), "=r"(f[3]) : "r"(addr));
}
__device__ __forceinline__ void cpasync16(uint32_t dst, const void* src) {
    asm volatile("cp.async.cg.shared.global [%0], [%1], 16;" :: "r"(dst), "l"(src));
}
#define CP_COMMIT() asm volatile("cp.async.commit_group;" ::: "memory")
#define CP_WAIT(n)  asm volatile("cp.async.wait_group %0;" :: "n"(n) : "memory")

// warp mma: D(16x8,f32) += A(16x16 bf16,row) * B(16x8 bf16,col)
__device__ __forceinline__ void mma16816(float* d, const uint32_t* a, const uint32_t* b) {
    asm volatile(
        "mma.sync.aligned.m16n8k16.row.col.f32.bf16.bf16.f32 "
        "{%0,%1,%2,%3}, {%4,%5,%6,%7}, {%8,%9}, {%0,%1,%2,%3};"
        : "+f"(d[0]), "+f"(d[1]), "+f"(d[2]), "+f"(d[3])
        : "r"(a[0]), "r"(a[1]), "r"(a[2]), "r"(a[3]), "r"(b[0]), "r"(b[1]));
}

// convert 8 fp32 -> 8 bf16, packed as uint4
__device__ __forceinline__ uint4 pack8(const float* v) {
    uint32_t h[4];
    #pragma unroll
    for (int i = 0; i < 4; i++) {
        __nv_bfloat16 h0 = __float2bfloat16_rn(v[2 * i]);
        __nv_bfloat16 h1 = __float2bfloat16_rn(v[2 * i + 1]);
        h[i] = (uint32_t)__bfloat16_as_ushort(h0) | ((uint32_t)__bfloat16_as_ushort(h1) << 16);
    }
    return make_uint4(h[0], h[1], h[2], h[3]);
}

// pack float2 -> bf16x2
__device__ __forceinline__ uint32_t packbf2(float a, float b) {
    __nv_bfloat16 h0 = __float2bfloat16_rn(a);
    __nv_bfloat16 h1 = __float2bfloat16_rn(b);
    return (uint32_t)__bfloat16_as_ushort(h0) | ((uint32_t)__bfloat16_as_ushort(h1) << 16);
}

// A tile geometry: bf16 [row][k], row stride 136 elems (272 B)
#define RSTRIDE 272
#define B_REGION 34816             // B fragments (32KB linear) + D staging (stride-68)
#define SM_LNQKV (34816 + 2 * B_REGION)  // 104448
#define SM_PROJ  67584             // max(A tile 34816, ts 128*132*4)

// ---------------------------------------------------------------------------
// Kernel 0: pre-fragment weights (bf16 hi) into per-lane LDG layout.
// ---------------------------------------------------------------------------
__global__ void prep_kernel(const float* __restrict__ qw, const float* __restrict__ pw) {
    int t = blockIdx.x * 256 + threadIdx.x;
    int lane = t & 31, nt = (t >> 5) & 15, ks = (t >> 9) & 7, chunk = t >> 12;
    int n = nt * 8 + (lane >> 2);
    int kb = ks * 16 + (lane & 3) * 2;
    if (t < 3 * 8 * 16 * 32) {
        const float* wr = qw + (chunk * 128 + n) * 128;
        float2 a = __ldg((const float2*)(wr + kb));
        float2 b = __ldg((const float2*)(wr + kb + 8));
        g_wfrag[t] = make_uint2(packbf2(a.x, a.y), packbf2(b.x, b.y));
    }
    if (t < 8 * 16 * 32) {
        const float* wr = pw + n * 128;
        float2 a = __ldg((const float2*)(wr + kb));
        float2 b = __ldg((const float2*)(wr + kb + 8));
        g_pfrag[t] = make_uint2(packbf2(a.x, a.y), packbf2(b.x, b.y));
    }
}

// ---------------------------------------------------------------------------
// Kernel 1: LN + QKV GEMM (single bf16); B smem-staged (hidden under LN);
// D staged through dead B region for coalesced fp16 output.  2 CTA/SM.
// smem: A [0,34816) | R0 [34816,69632) | R1 [69632,104448)
// ---------------------------------------------------------------------------
__global__ void __launch_bounds__(256, 2) lnqkv_mma(
    const float* __restrict__ x, const float* __restrict__ gam,
    const float* __restrict__ bet, const float* __restrict__ qb)
{
    extern __shared__ char smem[];
    const int tid = threadIdx.x, lane = tid & 31, wid = tid >> 5;
    const int vb = blockIdx.x * 128;
    const uint32_t sb = smem_u32(smem);

    // prefetch B chunk 0 into region 0 (linear, first 32KB)
    #pragma unroll
    for (int t = 0; t < 8; t++) {
        int idx = tid + t * 256;
        cpasync16(sb + 34816 + idx * 16, (const char*)g_wfrag + idx * 16);
    }
    CP_COMMIT();

    // ---- LayerNorm: 4 threads/voxel, 2 passes of 64 voxels ----
    #pragma unroll
    for (int vp = 0; vp < 2; vp++) {
        const int v = vp * 64 + (tid >> 2), q = tid & 3;
        float r[32];
        const float* xp = x + (q * 32) * NVOX + vb + v;
        #pragma unroll 8
        for (int i = 0; i < 32; i++) r[i] = xp[i * NVOX];
        float s = 0.f, s2 = 0.f;
        #pragma unroll
        for (int i = 0; i < 32; i++) { s += r[i]; s2 += r[i] * r[i]; }
        s  += __shfl_xor_sync(0xffffffffu, s, 1);  s  += __shfl_xor_sync(0xffffffffu, s, 2);
        s2 += __shfl_xor_sync(0xffffffffu, s2, 1); s2 += __shfl_xor_sync(0xffffffffu, s2, 2);
        float mu = s * (1.f / 128.f);
        float var = s2 * (1.f / 128.f) - mu * mu;
        float rs = rsqrtf(var + 1e-5f);
        #pragma unroll 8
        for (int i = 0; i < 32; i++) {
            int c = q * 32 + i;
            r[i] = (r[i] - mu) * rs * __ldg(&gam[c]) + __ldg(&bet[c]);
        }
        #pragma unroll
        for (int jj = 0; jj < 4; jj++) {
            int chunk = q * 4 + jj;
            *(uint4*)(smem + v * RSTRIDE + chunk * 16) = pack8(&r[8 * jj]);
        }
    }

    const int g = lane >> 2, t2 = lane & 3;
    const int m0 = (wid & 3) * 32, nhalf = wid >> 2, n0 = nhalf * 64;
    const uint32_t aA = sb + (m0 + (lane & 15)) * RSTRIDE + (lane >> 4) * 16;
    const int bidx = (nhalf * 256 + lane) * 8;
    const int n0h = nhalf * 32;

    #pragma unroll
    for (int nc = 0; nc < 3; nc++) {
        if (nc < 2) {
            uint32_t boff = 34816 + ((nc + 1) & 1) * B_REGION;
            #pragma unroll
            for (int t = 0; t < 8; t++) {
                int idx = tid + t * 256;
                cpasync16(sb + boff + idx * 16,
                          (const char*)g_wfrag + (nc + 1) * 32768 + idx * 16);
            }
            CP_COMMIT();
            CP_WAIT(1);
        } else {
            CP_WAIT(0);
        }
        __syncthreads();

        char* reg = smem + 34816 + (nc & 1) * B_REGION;
        const char* bbase = reg + bidx;

        float acc[2][8][4];
        #pragma unroll
        for (int nt = 0; nt < 8; nt++) {
            float b0 = __ldg(&qb[nc * 128 + n0 + nt * 8 + t2 * 2]);
            float b1 = __ldg(&qb[nc * 128 + n0 + nt * 8 + t2 * 2 + 1]);
            acc[0][nt][0] = b0; acc[0][nt][1] = b1; acc[0][nt][2] = b0; acc[0][nt][3] = b1;
            acc[1][nt][0] = b0; acc[1][nt][1] = b1; acc[1][nt][2] = b0; acc[1][nt][3] = b1;
        }

        #pragma unroll
        for (int ks = 0; ks < 8; ks++) {
            uint2 B[8];
            #pragma unroll
            for (int nt = 0; nt < 8; nt++)
                B[nt] = *(const uint2*)(bbase + (ks * 512 + nt * 32) * 8);
            uint32_t Ah[2][4];
            ldsm4(Ah[0], aA + ks * 32);
            ldsm4(Ah[1], aA + 16 * RSTRIDE + ks * 32);
            #pragma unroll
            for (int nt = 0; nt < 8; nt++) {
                uint32_t bh[2] = { B[nt].x, B[nt].y };
                mma16816(acc[0][nt], Ah[0], bh);
                mma16816(acc[1][nt], Ah[1], bh);
            }
        }
        __syncthreads();     // all warps done reading this B region

        // stage D into dead B region: [128 rows][stride 68 words] fp16x2
        uint32_t* st = (uint32_t*)reg;
        #pragma unroll
        for (int mt = 0; mt < 2; mt++) {
            int row = m0 + mt * 16 + g;
            #pragma unroll
            for (int nt = 0; nt < 8; nt++) {
                int cw = n0h + nt * 4 + t2;
                __half2 h0 = __floats2half2_rn(acc[mt][nt][0], acc[mt][nt][1]);
                __half2 h1 = __floats2half2_rn(acc[mt][nt][2], acc[mt][nt][3]);
                st[row * 68 + cw]       = *(uint32_t*)&h0;
                st[(row + 8) * 68 + cw] = *(uint32_t*)&h1;
            }
        }
        __syncthreads();

        // coalesced copy-out: 128 rows x 16B chunks (rows 256B contiguous)
        if (nc == 0) {
            for (int i = tid; i < 128 * 16; i += 256) {
                int row = i >> 4, ch = i & 15;
                uint4 t = *(const uint4*)&st[row * 68 + ch * 4];
                ((uint4*)g_qh)[(size_t)(vb + row) * 16 + ch] = t;
            }
        } else {
            int base4 = (nc == 1) ? 0 : 16;
            for (int i = tid; i < 128 * 16; i += 256) {
                int row = i >> 4, ch = i & 15;
                uint4 t = *(const uint4*)&st[row * 68 + ch * 4];
                ((uint4*)g_kv)[(size_t)(vb + row) * 32 + base4 + ch] = t;
            }
        }
        __syncthreads();     // region free before next prefetch targets it
    }
}

// ---------------------------------------------------------------------------
// Kernel 2: 27-neighbor attention, fp16 K/V/Q, single-phase halo, HFMA2.
// Output: bf16 voxel-major g_abf[v][128].  2 blocks/SM.
// ---------------------------------------------------------------------------
__global__ void __launch_bounds__(256, 2) attn_kernel() {
    extern __shared__ char smem[];
    char* ksm = smem;
    char* vsm = smem + 55296;
    const int tid = threadIdx.x;
    const int b = blockIdx.x;
    const int tx = b >> 6, ty = (b >> 3) & 7, tz = b & 7;
    const int hx0 = tx * 4 - 1, hy0 = ty * 4 - 1, hz0 = tz * 4 - 1;

    const int j = tid & 63, h = tid >> 6;
    const int lx = j >> 4, ly = (j >> 2) & 3, lz = j & 3;
    const int gx = tx * 4 + lx, gy = ty * 4 + ly, gz = tz * 4 + lz;
    const int gv0 = (gx << 10) + (gy << 5) + gz;

    for (int i = tid; i < 216 * 32; i += 256) {
        int p = i >> 5, c = i & 31;
        int hx = p / 36, r = p - hx * 36, hy = r / 6, hz = r - hy * 6;
        int ggx = min(max(hx0 + hx, 0), 31);
        int ggy = min(max(hy0 + hy, 0), 31);
        int ggz = min(max(hz0 + hz, 0), 31);
        int gv = (ggx << 10) + (ggy << 5) + ggz;
        uint4 t = __ldg((const uint4*)((const char*)g_kv + gv * 512 + c * 16));
        char* base = (c < 16) ? ksm : vsm;
        int cc = c & 15;
        *(uint4*)(base + p * 256 + ((cc ^ (p & 15)) << 4)) = t;
    }

    __half2 qh[16];
    {
        const __half2 s2 = __float2half2_rn(SCALE);
        const uint4* qp = (const uint4*)&g_qh[gv0 * 128 + h * 32];
        #pragma unroll
        for (int c = 0; c < 4; c++) {
            uint4 t = __ldg(qp + c);
            const __half2* q2 = (const __half2*)&t;
            qh[c * 4 + 0] = __hmul2(q2[0], s2);
            qh[c * 4 + 1] = __hmul2(q2[1], s2);
            qh[c * 4 + 2] = __hmul2(q2[2], s2);
            qh[c * 4 + 3] = __hmul2(q2[3], s2);
        }
    }
    __syncthreads();

    const int sx = min(max(gx - 1, 0), 29) - hx0;
    const int sy = min(max(gy - 1, 0), 29) - hy0;
    const int sz = min(max(gz - 1, 0), 29) - hz0;

    const __half2 z2 = __float2half2_rn(0.f);
    float sc[27];
    #pragma unroll
    for (int dx = 0; dx < 3; dx++)
    #pragma unroll
    for (int dy = 0; dy < 3; dy++)
    #pragma unroll
    for (int dz = 0; dz < 3; dz++) {
        int p = (sx + dx) * 36 + (sy + dy) * 6 + (sz + dz);
        const char* kb = ksm + p * 256;
        int psw = p & 15;
        __half2 a0 = z2, a1 = z2, a2 = z2, a3 = z2;
        #pragma unroll
        for (int cc = 0; cc < 4; cc++) {
            uint4 t = *(const uint4*)(kb + (((h * 4 + cc) ^ psw) << 4));
            const __half2* kk = (const __half2*)&t;
            a0 = __hfma2(qh[cc * 4 + 0], kk[0], a0);
            a1 = __hfma2(qh[cc * 4 + 1], kk[1], a1);
            a2 = __hfma2(qh[cc * 4 + 2], kk[2], a2);
            a3 = __hfma2(qh[cc * 4 + 3], kk[3], a3);
        }
        __half2 as = __hadd2(__hadd2(a0, a1), __hadd2(a2, a3));
        float2 f = __half22float2(as);
        sc[dx * 9 + dy * 3 + dz] = f.x + f.y;
    }

    float mx = sc[0];
    #pragma unroll
    for (int n = 1; n < 27; n++) mx = fmaxf(mx, sc[n]);
    float sum = 0.f;
    #pragma unroll
    for (int n = 0; n < 27; n++) { float e = __expf(sc[n] - mx); sc[n] = e; sum += e; }
    float inv = __fdividef(1.f, sum);

    __half2 out[16];
    #pragma unroll
    for (int i = 0; i < 16; i++) out[i] = z2;

    #pragma unroll
    for (int dx = 0; dx < 3; dx++)
    #pragma unroll
    for (int dy = 0; dy < 3; dy++)
    #pragma unroll
    for (int dz = 0; dz < 3; dz++) {
        int p = (sx + dx) * 36 + (sy + dy) * 6 + (sz + dz);
        const char* vbp = vsm + p * 256;
        int psw = p & 15;
        __half2 wh = __float2half2_rn(sc[dx * 9 + dy * 3 + dz]);
        #pragma unroll
        for (int cc = 0; cc < 4; cc++) {
            uint4 t = *(const uint4*)(vbp + (((h * 4 + cc) ^ psw) << 4));
            const __half2* vv = (const __half2*)&t;
            out[cc * 4 + 0] = __hfma2(wh, vv[0], out[cc * 4 + 0]);
            out[cc * 4 + 1] = __hfma2(wh, vv[1], out[cc * 4 + 1]);
            out[cc * 4 + 2] = __hfma2(wh, vv[2], out[cc * 4 + 2]);
            out[cc * 4 + 3] = __hfma2(wh, vv[3], out[cc * 4 + 3]);
        }
    }

    __syncthreads();
    uint32_t* buf = (uint32_t*)ksm;
    #pragma unroll
    for (int c = 0; c < 16; c++) {
        float2 f = __half22float2(out[c]);
        buf[j * 68 + h * 16 + c] = packbf2(f.x * inv, f.y * inv);
    }
    __syncthreads();
    for (int i = tid; i < 64 * 16; i += 256) {
        int v = i >> 4, ch = i & 15;
        uint4 t = *(const uint4*)&buf[v * 68 + ch * 4];
        int vlx = v >> 4, vly = (v >> 2) & 3, vlz = v & 3;
        int gv = (((tx * 4 + vlx) << 10) + ((ty * 4 + vly) << 5) + tz * 4 + vlz);
        g_abf[gv * 16 + ch] = t;
    }
}

// ---------------------------------------------------------------------------
// Kernel 3: proj GEMM (single bf16, B via LDG) + bias + residual.  2 CTA/SM.
// ---------------------------------------------------------------------------
__global__ void __launch_bounds__(256, 2) proj_mma(
    const float* __restrict__ x, const float* __restrict__ pb, float* __restrict__ out)
{
    extern __shared__ char smem[];
    const int tid = threadIdx.x, lane = tid & 31, wid = tid >> 5;
    const int vb = blockIdx.x * 128;
    const uint32_t sb = smem_u32(smem);

    {
        const char* src = (const char*)g_abf + (size_t)vb * 256;
        #pragma unroll
        for (int t = 0; t < 8; t++) {
            int idx = tid + t * 256;
            int v = idx >> 4, ch = idx & 15;
            cpasync16(sb + v * RSTRIDE + ch * 16, src + idx * 16);
        }
        CP_COMMIT();
        CP_WAIT(0);
    }
    __syncthreads();

    const int g = lane >> 2, t2 = lane & 3;
    const int m0 = (wid & 3) * 32, nhalf = wid >> 2, n0 = nhalf * 64;
    const uint32_t aA = sb + (m0 + (lane & 15)) * RSTRIDE + (lane >> 4) * 16;
    const uint2* __restrict__ bp = g_pfrag + nhalf * 256 + lane;

    float acc[2][8][4];
    #pragma unroll
    for (int nt = 0; nt < 8; nt++) {
        float b0 = __ldg(&pb[n0 + nt * 8 + t2 * 2]);
        float b1 = __ldg(&pb[n0 + nt * 8 + t2 * 2 + 1]);
        acc[0][nt][0] = b0; acc[0][nt][1] = b1; acc[0][nt][2] = b0; acc[0][nt][3] = b1;
        acc[1][nt][0] = b0; acc[1][nt][1] = b1; acc[1][nt][2] = b0; acc[1][nt][3] = b1;
    }

    #pragma unroll
    for (int ks = 0; ks < 8; ks++) {
        uint2 B[8];
        #pragma unroll
        for (int nt = 0; nt < 8; nt++)
            B[nt] = __ldg(bp + ks * 512 + nt * 32);
        uint32_t Ah[2][4];
        ldsm4(Ah[0], aA + ks * 32);
        ldsm4(Ah[1], aA + 16 * RSTRIDE + ks * 32);
        #pragma unroll
        for (int nt = 0; nt < 8; nt++) {
            uint32_t bh[2] = { B[nt].x, B[nt].y };
            mma16816(acc[0][nt], Ah[0], bh);
            mma16816(acc[1][nt], Ah[1], bh);
        }
    }

    __syncthreads();
    float* ts = (float*)smem;
    #pragma unroll
    for (int mt = 0; mt < 2; mt++) {
        int row = m0 + mt * 16 + g;
        #pragma unroll
        for (int nt = 0; nt < 8; nt++) {
            int col = n0 + nt * 8 + t2 * 2;
            ts[col * 132 + row]           = acc[mt][nt][0];
            ts[(col + 1) * 132 + row]     = acc[mt][nt][1];
            ts[col * 132 + row + 8]       = acc[mt][nt][2];
            ts[(col + 1) * 132 + row + 8] = acc[mt][nt][3];
        }
    }
    __syncthreads();

    for (int i = tid; i < 128 * 32; i += 256) {
        int c = i >> 5, vq = i & 31;
        int off = c * NVOX + vb + vq * 4;
        float4 t = *(const float4*)&ts[c * 132 + vq * 4];
        float4 xr = *(const float4*)&x[off];
        *(float4*)&out[off] = make_float4(t.x + xr.x, t.y + xr.y, t.z + xr.z, t.w + xr.w);
    }
}

// ---------------------------------------------------------------------------
extern "C" void kernel_launch(void* const* d_in, const int* in_sizes, int n_in,
                              void* d_out, int out_size)
{
    const float* x   = (const float*)d_in[0];
    const float* gam = (const float*)d_in[1];
    const float* bet = (const float*)d_in[2];
    const float* qw  = (const float*)d_in[3];
    const float* qb  = (const float*)d_in[4];
    const float* pw  = (const float*)d_in[5];
    const float* pb  = (const float*)d_in[6];
    float* out = (float*)d_out;

    const int SMEM_ATTN = 110592;

    cudaFuncSetAttribute(lnqkv_mma,   cudaFuncAttributeMaxDynamicSharedMemorySize, SM_LNQKV);
    cudaFuncSetAttribute(attn_kernel, cudaFuncAttributeMaxDynamicSharedMemorySize, SMEM_ATTN);
    cudaFuncSetAttribute(proj_mma,    cudaFuncAttributeMaxDynamicSharedMemorySize, SM_PROJ);

    prep_kernel<<<48, 256>>>(qw, pw);
    lnqkv_mma<<<256, 256, SM_LNQKV>>>(x, gam, bet, qb);
    attn_kernel<<<512, 256, SMEM_ATTN>>>();
    proj_mma<<<256, 256, SM_PROJ>>>(x, pb, out);
}